// round 3
// baseline (speedup 1.0000x reference)
#include <cuda_runtime.h>
#include <math.h>

#define N 1024
#define E 128
#define NEG 0.2f

#define BM 128            // j-rows per CTA in big kernel
#define ASTR 132          // padded A-tile stride (bank-conflict avoidance)
#define SMEM_BIG ((BM*ASTR + E*E + E) * sizeof(float))

// ---- scratch (no allocs allowed) ----
__device__ float g_wf[N * E];
__device__ float g_base[N * E];
__device__ float g_s[N];
__device__ float g_wa2[E];
__device__ float g_logits[(size_t)N * N];

__device__ __forceinline__ float lrelu(float x) { return x >= 0.f ? x : NEG * x; }

// ---------------- small precompute kernels ----------------

// wf[i][l] = sum_k embs[i][k] * W[k][l]
__global__ void k_wf(const float* __restrict__ embs, const float* __restrict__ W) {
    __shared__ float es[E];
    int i = blockIdx.x, l = threadIdx.x;
    es[l] = embs[i * E + l];
    __syncthreads();
    float acc = 0.f;
#pragma unroll 8
    for (int k = 0; k < E; k++) acc = fmaf(es[k], W[k * E + l], acc);
    g_wf[i * E + l] = acc;
}

// w_a2[m] = sum_k W[m][k] * a_W[E + k]
__global__ void k_wa2(const float* __restrict__ W, const float* __restrict__ aW) {
    __shared__ float a2s[E];
    int m = threadIdx.x;
    a2s[m] = aW[E + m];
    __syncthreads();
    float acc = 0.f;
#pragma unroll 8
    for (int k = 0; k < E; k++) acc = fmaf(W[m * E + k], a2s[k], acc);
    g_wa2[m] = acc;
}

// base[j][l] = sum_k wf[j][k]*pc_W[k][l] + pc_b[l] ;  s[i] = sum_k wf[i][k]*a_W[k]
__global__ void k_base(const float* __restrict__ pcW, const float* __restrict__ pcb,
                       const float* __restrict__ aW) {
    __shared__ float ws[E];
    __shared__ float red[E];
    int i = blockIdx.x, l = threadIdx.x;
    float w = g_wf[i * E + l];
    ws[l] = w;
    red[l] = w * aW[l];
    __syncthreads();
    float acc = pcb[l];
#pragma unroll 8
    for (int k = 0; k < E; k++) acc = fmaf(ws[k], pcW[k * E + l], acc);
    g_base[i * E + l] = acc;
    for (int off = 64; off > 0; off >>= 1) {
        __syncthreads();
        if (l < off) red[l] += red[l + off];
    }
    __syncthreads();
    if (l == 0) g_s[i] = red[0];
}

// ---------------- the big fused GEMM + attention-logit kernel ----------------
// For block (bx, by=i): rows j in [bx*128, bx*128+128).
//   t[j][l]       = pde[i][j][:] . pc_Wp[:,l]         (128x128x128 GEMM tile)
//   logits[i][j]  = lrelu( s[i] + sum_l lrelu(base[j][l] + t[j][l]) * w_a2[l] + a_b )
//   masked by adj.  NOTE: base is indexed by j (c_term[None,:,:] broadcast), not i!
__global__ void __launch_bounds__(256, 1)
k_big(const float* __restrict__ pde, const float* __restrict__ pcW,
      const int* __restrict__ adj, const float* __restrict__ ab_ptr) {
    extern __shared__ float sm[];
    float* As = sm;                 // BM x ASTR  (pde tile; later overlaid with base tile)
    float* Bs = sm + BM * ASTR;     // E x E  (pc_Wp, row k major)
    float* w_s = Bs + E * E;        // E

    const int i = blockIdx.y;
    const int j0 = blockIdx.x * BM;
    const int tid = threadIdx.x;

    // Load A tile: pde[i][j0..j0+127][0..127], 4096 float4s by 256 threads.
    const float4* gA4 = (const float4*)(pde + ((size_t)i * N + j0) * E);
#pragma unroll
    for (int t = 0; t < 16; t++) {
        int idx = tid + t * 256;
        int row = idx >> 5, c4 = idx & 31;
        float4 v = gA4[idx];
        *(float4*)(As + row * ASTR + (c4 << 2)) = v;
    }
    // Load B = pc_Wp = pc_W + E*E (row k major), direct copy.
    const float4* gB4 = (const float4*)(pcW + E * E);
    float4* Bs4 = (float4*)Bs;
#pragma unroll
    for (int t = 0; t < 16; t++) Bs4[tid + t * 256] = gB4[tid + t * 256];

    if (tid < E) w_s[tid] = g_wa2[tid];
    __syncthreads();

    const int tx = tid & 15;   // col group
    const int ty = tid >> 4;   // row group

    float acc[8][8];
#pragma unroll
    for (int r = 0; r < 8; r++)
#pragma unroll
        for (int c = 0; c < 8; c++) acc[r][c] = 0.f;

#pragma unroll 4
    for (int k = 0; k < E; k++) {
        float a[8], b[8];
#pragma unroll
        for (int r = 0; r < 8; r++) a[r] = As[(ty + (r << 4)) * ASTR + k];
#pragma unroll
        for (int c = 0; c < 8; c++) b[c] = Bs[(k << 7) + tx + (c << 4)];
#pragma unroll
        for (int r = 0; r < 8; r++)
#pragma unroll
            for (int c = 0; c < 8; c++) acc[r][c] = fmaf(a[r], b[c], acc[r][c]);
    }

    // ---- overlay: load base[j0..j0+127][0..127] into the (now dead) As region ----
    __syncthreads();
    const float4* gBase4 = (const float4*)(g_base + (size_t)j0 * E);
#pragma unroll
    for (int t = 0; t < 16; t++) {
        int idx = tid + t * 256;
        int row = idx >> 5, c4 = idx & 31;
        float4 v = gBase4[idx];
        *(float4*)(As + row * ASTR + (c4 << 2)) = v;
    }
    __syncthreads();

    const float s_i = g_s[i];
    const float ab = ab_ptr[0];

#pragma unroll
    for (int r = 0; r < 8; r++) {
        const int row = ty + (r << 4);
        float part = 0.f;
#pragma unroll
        for (int c = 0; c < 8; c++) {
            int col = tx + (c << 4);
            part = fmaf(lrelu(As[row * ASTR + col] + acc[r][c]), w_s[col], part);
        }
        // reduce across the 16 lanes that share this row (contiguous half-warp)
#pragma unroll
        for (int off = 8; off > 0; off >>= 1)
            part += __shfl_down_sync(0xffffffffu, part, off, 16);
        if (tx == 0) {
            int j = j0 + row;
            float lg = lrelu(s_i + part + ab);
            size_t idx = (size_t)i * N + j;
            g_logits[idx] = (adj[idx] == 1) ? lg : -1e30f;
        }
    }
}

// ---------------- softmax + attn@embs + concat ----------------
#define RPB 4
__global__ void __launch_bounds__(128)
k_out(const float* __restrict__ embs, float* __restrict__ out) {
    __shared__ float attn[RPB][N];   // 16KB
    __shared__ float red[E];
    const int i0 = blockIdx.x * RPB;
    const int t = threadIdx.x;

    float inv[RPB];
#pragma unroll
    for (int r = 0; r < RPB; r++) {
        const float* lg = g_logits + (size_t)(i0 + r) * N;
        // max
        float m = -1e30f;
#pragma unroll
        for (int q = 0; q < N / E; q++) m = fmaxf(m, lg[t + q * E]);
        red[t] = m;
        for (int off = 64; off > 0; off >>= 1) {
            __syncthreads();
            if (t < off) red[t] = fmaxf(red[t], red[t + off]);
        }
        __syncthreads();
        m = red[0];
        __syncthreads();
        // exp + sum
        float s = 0.f;
#pragma unroll
        for (int q = 0; q < N / E; q++) {
            float e = expf(lg[t + q * E] - m);
            attn[r][t + q * E] = e;
            s += e;
        }
        red[t] = s;
        for (int off = 64; off > 0; off >>= 1) {
            __syncthreads();
            if (t < off) red[t] += red[t + off];
        }
        __syncthreads();
        inv[r] = 1.f / red[0];
        __syncthreads();
    }

    // nbc[i][t] = (1/sum) * sum_j attn[i][j] * embs[j][t]
    float acc[RPB];
#pragma unroll
    for (int r = 0; r < RPB; r++) acc[r] = 0.f;
#pragma unroll 8
    for (int j = 0; j < N; j++) {
        float ev = embs[j * E + t];
#pragma unroll
        for (int r = 0; r < RPB; r++) acc[r] = fmaf(attn[r][j], ev, acc[r]);
    }
#pragma unroll
    for (int r = 0; r < RPB; r++) {
        int i = i0 + r;
        out[(size_t)i * (2 * E) + t] = embs[i * E + t];
        out[(size_t)i * (2 * E) + E + t] = acc[r] * inv[r];
    }
}

// ---------------- launch ----------------
extern "C" void kernel_launch(void* const* d_in, const int* in_sizes, int n_in,
                              void* d_out, int out_size) {
    const float* embs = (const float*)d_in[0];
    const int*   adj  = (const int*)d_in[1];
    const float* pde  = (const float*)d_in[2];
    const float* W    = (const float*)d_in[3];
    const float* pcW  = (const float*)d_in[4];
    const float* pcb  = (const float*)d_in[5];
    const float* aW   = (const float*)d_in[6];
    const float* ab   = (const float*)d_in[7];
    float* out = (float*)d_out;

    // idempotent, cheap; needed for >48KB dynamic smem
    cudaFuncSetAttribute(k_big, cudaFuncAttributeMaxDynamicSharedMemorySize,
                         (int)SMEM_BIG);

    k_wf<<<N, E>>>(embs, W);
    k_wa2<<<1, E>>>(W, aW);
    k_base<<<N, E>>>(pcW, pcb, aW);
    k_big<<<dim3(N / BM, N), 256, SMEM_BIG>>>(pde, pcW, adj, ab);
    k_out<<<N / RPB, 128>>>(embs, out);
}

// round 5
// speedup vs baseline: 1.1872x; 1.1872x over previous
#include <cuda_runtime.h>
#include <mma.h>
#include <math.h>
#include <cstdint>

using namespace nvcuda;

#define N 1024
#define E 128
#define NEG 0.2f

#define I_PER_CTA 8
#define LDA 132                    // padded float stride
#define TILE_F (128 * LDA)         // floats per 128x128 tile buffer
#define SMEM_DYN ((3 * TILE_F + 128) * sizeof(float))

// ---- scratch ----
__device__ float g_wf[N * E];
__device__ float g_base[N * E];
__device__ float g_s[N];
__device__ float g_wa2[E];
__device__ float g_logits[(size_t)N * N];

__device__ __forceinline__ float lrelu(float x) { return fmaxf(x, NEG * x); }

__device__ __forceinline__ uint32_t smem_u32(const void* p) {
    return (uint32_t)__cvta_generic_to_shared(p);
}
__device__ __forceinline__ void cp16(uint32_t s, const void* g) {
    asm volatile("cp.async.cg.shared.global [%0], [%1], 16;" :: "r"(s), "l"(g));
}
__device__ __forceinline__ void cp_commit() {
    asm volatile("cp.async.commit_group;" ::: "memory");
}
template <int K>
__device__ __forceinline__ void cp_wait() {
    asm volatile("cp.async.wait_group %0;" :: "n"(K) : "memory");
}

// ---------------- small precompute kernels ----------------
__global__ void k_wf(const float* __restrict__ embs, const float* __restrict__ W) {
    __shared__ float es[E];
    int i = blockIdx.x, l = threadIdx.x;
    es[l] = embs[i * E + l];
    __syncthreads();
    float acc = 0.f;
#pragma unroll 8
    for (int k = 0; k < E; k++) acc = fmaf(es[k], W[k * E + l], acc);
    g_wf[i * E + l] = acc;
}

__global__ void k_wa2(const float* __restrict__ W, const float* __restrict__ aW) {
    __shared__ float a2s[E];
    int m = threadIdx.x;
    a2s[m] = aW[E + m];
    __syncthreads();
    float acc = 0.f;
#pragma unroll 8
    for (int k = 0; k < E; k++) acc = fmaf(W[m * E + k], a2s[k], acc);
    g_wa2[m] = acc;
}

__global__ void k_base(const float* __restrict__ pcW, const float* __restrict__ pcb,
                       const float* __restrict__ aW) {
    __shared__ float ws[E];
    __shared__ float red[E];
    int i = blockIdx.x, l = threadIdx.x;
    float w = g_wf[i * E + l];
    ws[l] = w;
    red[l] = w * aW[l];
    __syncthreads();
    float acc = pcb[l];
#pragma unroll 8
    for (int k = 0; k < E; k++) acc = fmaf(ws[k], pcW[k * E + l], acc);
    g_base[i * E + l] = acc;
    for (int off = 64; off > 0; off >>= 1) {
        __syncthreads();
        if (l < off) red[l] += red[l + off];
    }
    __syncthreads();
    if (l == 0) g_s[i] = red[0];
}

// ---------------- wmma tf32 big kernel ----------------
// grid (8, 128): blockIdx.x = j-block (128 rows), blockIdx.y = i-chunk (8 i's).
// Per i:  t[j][l] = pde[i][j][:] . pc_Wp[:,l]   (128x128x128, tf32 tensor cores)
//         logits[i][j] = lrelu(s[i] + sum_l lrelu(base[j][l]+t[j][l])*wa2[l] + ab)
__global__ void __launch_bounds__(256, 1)
k_big(const float* __restrict__ pde, const float* __restrict__ pcW,
      const int* __restrict__ adj, const float* __restrict__ ab_ptr) {
    extern __shared__ float sm[];
    float* Abuf[2] = { sm, sm + TILE_F };
    float* Bs = sm + 2 * TILE_F;
    float* wa2s = sm + 3 * TILE_F;

    const int tid = threadIdx.x;
    const int wid = tid >> 5;
    const int j0 = blockIdx.x * 128;
    const int i_base = blockIdx.y * I_PER_CTA;
    const float ab = ab_ptr[0];

    // ---- prologue: cp.async B (pc_Wp) and A tile 0 ----
    const float* pcWp = pcW + E * E;
#pragma unroll
    for (int t = 0; t < 16; t++) {
        int idx = tid + t * 256;             // 4096 16B-chunks
        int row = idx >> 5, c4 = (idx & 31) << 2;
        cp16(smem_u32(Bs + row * LDA + c4), pcWp + row * E + c4);
    }
    cp_commit();
    const float* gA0 = pde + ((size_t)i_base * N + j0) * E;
#pragma unroll
    for (int t = 0; t < 16; t++) {
        int idx = tid + t * 256;
        int row = idx >> 5, c4 = (idx & 31) << 2;
        cp16(smem_u32(Abuf[0] + row * LDA + c4), gA0 + (size_t)row * E + c4);
    }
    cp_commit();
    if (tid < E) wa2s[tid] = g_wa2[tid];
    cp_wait<0>();
    __syncthreads();

    const int wr = (wid & 3) * 32;   // warp row base
    const int wc = (wid >> 2) * 64;  // warp col base

    for (int s = 0; s < I_PER_CTA; s++) {
        float* A = Abuf[s & 1];
        float* Cprev = Abuf[1 - (s & 1)];

        // ---- epilogue for tile s-1 (reads Cprev; overlaps nothing dependent on A[s]) ----
        if (s > 0) {
            const int i = i_base + s - 1;
            const int row = tid >> 1, h = tid & 1;
            const float* cr = Cprev + row * LDA + h * 64;
            const float* br = g_base + (size_t)(j0 + row) * E + h * 64;
            const float* wr2 = wa2s + h * 64;
            float part = 0.f;
#pragma unroll
            for (int c = 0; c < 64; c += 4) {
                float4 cv = *(const float4*)(cr + c);
                float4 bv = *(const float4*)(br + c);
                part = fmaf(lrelu(cv.x + bv.x), wr2[c], part);
                part = fmaf(lrelu(cv.y + bv.y), wr2[c + 1], part);
                part = fmaf(lrelu(cv.z + bv.z), wr2[c + 2], part);
                part = fmaf(lrelu(cv.w + bv.w), wr2[c + 3], part);
            }
            part += __shfl_xor_sync(0xffffffffu, part, 1);
            if (h == 0) {
                float lg = lrelu(g_s[i] + part + ab);
                size_t oidx = (size_t)i * N + j0 + row;
                g_logits[oidx] = (adj[oidx] == 1) ? lg : -1e30f;
            }
            __syncthreads();   // Cprev fully consumed before refill
        }

        // ---- issue A[s+1] into Cprev region (overlaps the mma below) ----
        if (s + 1 < I_PER_CTA) {
            const float* gA = pde + ((size_t)(i_base + s + 1) * N + j0) * E;
#pragma unroll
            for (int t = 0; t < 16; t++) {
                int idx = tid + t * 256;
                int row = idx >> 5, c4 = (idx & 31) << 2;
                cp16(smem_u32(Cprev + row * LDA + c4), gA + (size_t)row * E + c4);
            }
            cp_commit();
            cp_wait<1>();      // A[s] complete; A[s+1] stays in flight
        } else {
            cp_wait<0>();
        }
        __syncthreads();

        // ---- tf32 wmma: 128x128x128 ----
        wmma::fragment<wmma::accumulator, 16, 16, 8, float> fc[2][4];
#pragma unroll
        for (int r = 0; r < 2; r++)
#pragma unroll
            for (int c = 0; c < 4; c++) wmma::fill_fragment(fc[r][c], 0.f);

#pragma unroll
        for (int ks = 0; ks < 16; ks++) {
            const int k0 = ks * 8;
            wmma::fragment<wmma::matrix_a, 16, 16, 8, wmma::precision::tf32, wmma::row_major> fa[2];
            wmma::fragment<wmma::matrix_b, 16, 16, 8, wmma::precision::tf32, wmma::row_major> fb[4];
#pragma unroll
            for (int r = 0; r < 2; r++) {
                wmma::load_matrix_sync(fa[r], A + (wr + r * 16) * LDA + k0, LDA);
#pragma unroll
                for (int t = 0; t < fa[r].num_elements; t++)
                    fa[r].x[t] = wmma::__float_to_tf32(fa[r].x[t]);
            }
#pragma unroll
            for (int c = 0; c < 4; c++) {
                wmma::load_matrix_sync(fb[c], Bs + k0 * LDA + wc + c * 16, LDA);
#pragma unroll
                for (int t = 0; t < fb[c].num_elements; t++)
                    fb[c].x[t] = wmma::__float_to_tf32(fb[c].x[t]);
            }
#pragma unroll
            for (int r = 0; r < 2; r++)
#pragma unroll
                for (int c = 0; c < 4; c++)
                    wmma::mma_sync(fc[r][c], fa[r], fb[c], fc[r][c]);
        }

        __syncthreads();       // all warps done reading A[s]
#pragma unroll
        for (int r = 0; r < 2; r++)
#pragma unroll
            for (int c = 0; c < 4; c++)
                wmma::store_matrix_sync(A + (wr + r * 16) * LDA + wc + c * 16,
                                        fc[r][c], LDA, wmma::mem_row_major);
        __syncthreads();       // C[s] visible for next-iter epilogue
    }

    // ---- final epilogue: tile 7, C in Abuf[1] ----
    {
        const int i = i_base + I_PER_CTA - 1;
        float* Clast = Abuf[(I_PER_CTA - 1) & 1];
        const int row = tid >> 1, h = tid & 1;
        const float* cr = Clast + row * LDA + h * 64;
        const float* br = g_base + (size_t)(j0 + row) * E + h * 64;
        const float* wr2 = wa2s + h * 64;
        float part = 0.f;
#pragma unroll
        for (int c = 0; c < 64; c += 4) {
            float4 cv = *(const float4*)(cr + c);
            float4 bv = *(const float4*)(br + c);
            part = fmaf(lrelu(cv.x + bv.x), wr2[c], part);
            part = fmaf(lrelu(cv.y + bv.y), wr2[c + 1], part);
            part = fmaf(lrelu(cv.z + bv.z), wr2[c + 2], part);
            part = fmaf(lrelu(cv.w + bv.w), wr2[c + 3], part);
        }
        part += __shfl_xor_sync(0xffffffffu, part, 1);
        if (h == 0) {
            float lg = lrelu(g_s[i] + part + ab);
            size_t oidx = (size_t)i * N + j0 + row;
            g_logits[oidx] = (adj[oidx] == 1) ? lg : -1e30f;
        }
    }
}

// ---------------- softmax + attn@embs + concat ----------------
#define RPB 4
__global__ void __launch_bounds__(128)
k_out(const float* __restrict__ embs, float* __restrict__ out) {
    __shared__ float attn[RPB][N];
    __shared__ float red[E];
    const int i0 = blockIdx.x * RPB;
    const int t = threadIdx.x;

    float inv[RPB];
#pragma unroll
    for (int r = 0; r < RPB; r++) {
        const float* lg = g_logits + (size_t)(i0 + r) * N;
        float m = -1e30f;
#pragma unroll
        for (int q = 0; q < N / E; q++) m = fmaxf(m, lg[t + q * E]);
        red[t] = m;
        for (int off = 64; off > 0; off >>= 1) {
            __syncthreads();
            if (t < off) red[t] = fmaxf(red[t], red[t + off]);
        }
        __syncthreads();
        m = red[0];
        __syncthreads();
        float s = 0.f;
#pragma unroll
        for (int q = 0; q < N / E; q++) {
            float e = expf(lg[t + q * E] - m);
            attn[r][t + q * E] = e;
            s += e;
        }
        red[t] = s;
        for (int off = 64; off > 0; off >>= 1) {
            __syncthreads();
            if (t < off) red[t] += red[t + off];
        }
        __syncthreads();
        inv[r] = 1.f / red[0];
        __syncthreads();
    }

    float acc[RPB];
#pragma unroll
    for (int r = 0; r < RPB; r++) acc[r] = 0.f;
#pragma unroll 8
    for (int j = 0; j < N; j++) {
        float ev = embs[j * E + t];
#pragma unroll
        for (int r = 0; r < RPB; r++) acc[r] = fmaf(attn[r][j], ev, acc[r]);
    }
#pragma unroll
    for (int r = 0; r < RPB; r++) {
        int i = i0 + r;
        out[(size_t)i * (2 * E) + t] = embs[i * E + t];
        out[(size_t)i * (2 * E) + E + t] = acc[r] * inv[r];
    }
}

// ---------------- launch ----------------
extern "C" void kernel_launch(void* const* d_in, const int* in_sizes, int n_in,
                              void* d_out, int out_size) {
    const float* embs = (const float*)d_in[0];
    const int*   adj  = (const int*)d_in[1];
    const float* pde  = (const float*)d_in[2];
    const float* W    = (const float*)d_in[3];
    const float* pcW  = (const float*)d_in[4];
    const float* pcb  = (const float*)d_in[5];
    const float* aW   = (const float*)d_in[6];
    const float* ab   = (const float*)d_in[7];
    float* out = (float*)d_out;

    cudaFuncSetAttribute(k_big, cudaFuncAttributeMaxDynamicSharedMemorySize,
                         (int)SMEM_DYN);

    k_wf<<<N, E>>>(embs, W);
    k_wa2<<<1, E>>>(W, aW);
    k_base<<<N, E>>>(pcW, pcb, aW);
    k_big<<<dim3(8, N / I_PER_CTA), 256, SMEM_DYN>>>(pde, pcW, adj, ab);
    k_out<<<N / RPB, 128>>>(embs, out);
}

// round 6
// speedup vs baseline: 1.7257x; 1.4536x over previous
#include <cuda_runtime.h>
#include <cuda_bf16.h>
#include <mma.h>
#include <math.h>
#include <cstdint>

using namespace nvcuda;

#define N 1024
#define E 128
#define NEG 0.2f

#define I_PER_CTA 8
#define LDA_H 136                 // bf16 elements per padded row (272 B)
#define LDC 132                   // fp32 C stride
// smem byte offsets
#define OFF_A0 0
#define OFF_A1 34816
#define OFF_B  69632
#define OFF_C  104448
#define OFF_W  172032
#define SMEM_DYN (OFF_W + 512 + 64)

// ---- scratch ----
__device__ float g_wf[N * E];
__device__ float g_base[N * E];
__device__ float g_s[N];
__device__ float g_wa2[E];
__device__ float g_logits[(size_t)N * N];
__device__ __nv_bfloat16 g_Bb[E * E];   // pc_Wp in bf16, [k][n] row-major

__device__ __forceinline__ float lrelu(float x) { return fmaxf(x, NEG * x); }

// ---------------- small precompute kernels ----------------
__global__ void k_wf(const float* __restrict__ embs, const float* __restrict__ W) {
    __shared__ float es[E];
    int i = blockIdx.x, l = threadIdx.x;
    es[l] = embs[i * E + l];
    __syncthreads();
    float acc = 0.f;
#pragma unroll 8
    for (int k = 0; k < E; k++) acc = fmaf(es[k], W[k * E + l], acc);
    g_wf[i * E + l] = acc;
}

__global__ void k_wa2(const float* __restrict__ W, const float* __restrict__ aW) {
    __shared__ float a2s[E];
    int m = threadIdx.x;
    a2s[m] = aW[E + m];
    __syncthreads();
    float acc = 0.f;
#pragma unroll 8
    for (int k = 0; k < E; k++) acc = fmaf(W[m * E + k], a2s[k], acc);
    g_wa2[m] = acc;
}

__global__ void k_base(const float* __restrict__ pcW, const float* __restrict__ pcb,
                       const float* __restrict__ aW) {
    __shared__ float ws[E];
    __shared__ float red[E];
    int i = blockIdx.x, l = threadIdx.x;
    float w = g_wf[i * E + l];
    ws[l] = w;
    red[l] = w * aW[l];
    __syncthreads();
    float acc = pcb[l];
#pragma unroll 8
    for (int k = 0; k < E; k++) acc = fmaf(ws[k], pcW[k * E + l], acc);
    g_base[i * E + l] = acc;
    for (int off = 64; off > 0; off >>= 1) {
        __syncthreads();
        if (l < off) red[l] += red[l + off];
    }
    __syncthreads();
    if (l == 0) g_s[i] = red[0];
}

// g_Bb[k][n] = bf16(pc_Wp[k][n])
__global__ void k_bb(const float* __restrict__ pcW) {
    int idx = blockIdx.x * 128 + threadIdx.x;
    g_Bb[idx] = __float2bfloat16(pcW[E * E + idx]);
}

// ---------------- bf16 wmma big kernel ----------------
// grid (8, 128): blockIdx.x = j-block (128 rows), blockIdx.y = i-chunk (8 i's).
__global__ void __launch_bounds__(512, 1)
k_big(const float* __restrict__ pde, const int* __restrict__ adj,
      const float* __restrict__ ab_ptr) {
    extern __shared__ char sm[];
    __nv_bfloat16* Ab[2] = { (__nv_bfloat16*)(sm + OFF_A0), (__nv_bfloat16*)(sm + OFF_A1) };
    __nv_bfloat16* Bb = (__nv_bfloat16*)(sm + OFF_B);
    float* Cs = (float*)(sm + OFF_C);
    float* wa2s = (float*)(sm + OFF_W);

    const int tid = threadIdx.x;
    const int wid = tid >> 5;
    const int j0 = blockIdx.x * 128;
    const int i_base = blockIdx.y * I_PER_CTA;
    const float ab = ab_ptr[0];

    // ---- prologue: B (bf16 copy) + A0 (fp32->bf16) + wa2 ----
#pragma unroll
    for (int t = 0; t < 4; t++) {
        int chunk = tid + t * 512;             // 2048 chunks of 8 bf16
        int row = chunk >> 4, g = chunk & 15;
        *(uint4*)(Bb + row * LDA_H + g * 8) = *(const uint4*)(g_Bb + row * E + g * 8);
    }
    {
        const float* gA = pde + ((size_t)i_base * N + j0) * E;
#pragma unroll
        for (int t = 0; t < 4; t++) {
            int chunk = tid + t * 512;         // 2048 chunks of 8 floats
            int row = chunk >> 4, c8 = (chunk & 15) * 8;
            const float4* g = (const float4*)(gA + (size_t)row * E + c8);
            float4 v0 = g[0], v1 = g[1];
            __nv_bfloat162 p0 = __floats2bfloat162_rn(v0.x, v0.y);
            __nv_bfloat162 p1 = __floats2bfloat162_rn(v0.z, v0.w);
            __nv_bfloat162 p2 = __floats2bfloat162_rn(v1.x, v1.y);
            __nv_bfloat162 p3 = __floats2bfloat162_rn(v1.z, v1.w);
            uint4 o;
            o.x = *(uint32_t*)&p0; o.y = *(uint32_t*)&p1;
            o.z = *(uint32_t*)&p2; o.w = *(uint32_t*)&p3;
            *(uint4*)(Ab[0] + row * LDA_H + c8) = o;
        }
    }
    if (tid < E) wa2s[tid] = g_wa2[tid];
    __syncthreads();

    const int wr = (wid & 3) * 32;    // warp row base
    const int wc = (wid >> 2) * 32;   // warp col base

    for (int s = 0; s < I_PER_CTA; s++) {
        __nv_bfloat16* A = Ab[s & 1];

        // 1) issue LDG for next A tile into regs (latency overlaps epilogue+mma)
        float4 stage[8];
        if (s + 1 < I_PER_CTA) {
            const float* gA = pde + ((size_t)(i_base + s + 1) * N + j0) * E;
#pragma unroll
            for (int t = 0; t < 4; t++) {
                int chunk = tid + t * 512;
                int row = chunk >> 4, c8 = (chunk & 15) * 8;
                const float4* g = (const float4*)(gA + (size_t)row * E + c8);
                stage[2 * t] = g[0];
                stage[2 * t + 1] = g[1];
            }
        }

        // 2) epilogue for tile s-1 (C in Cs, synced at end of prev iter)
        if (s > 0) {
            const int i = i_base + s - 1;
            const int row = tid >> 2, q = tid & 3;
            const float* cr = Cs + row * LDC + q * 32;
            const float* br = g_base + (size_t)(j0 + row) * E + q * 32;
            const float* w2 = wa2s + q * 32;
            float part = 0.f;
#pragma unroll
            for (int c = 0; c < 32; c += 4) {
                float4 cv = *(const float4*)(cr + c);
                float4 bv = *(const float4*)(br + c);
                part = fmaf(lrelu(cv.x + bv.x), w2[c], part);
                part = fmaf(lrelu(cv.y + bv.y), w2[c + 1], part);
                part = fmaf(lrelu(cv.z + bv.z), w2[c + 2], part);
                part = fmaf(lrelu(cv.w + bv.w), w2[c + 3], part);
            }
            part += __shfl_xor_sync(0xffffffffu, part, 1);
            part += __shfl_xor_sync(0xffffffffu, part, 2);
            if (q == 0) {
                float lg = lrelu(g_s[i] + part + ab);
                size_t oidx = (size_t)i * N + j0 + row;
                g_logits[oidx] = (adj[oidx] == 1) ? lg : -1e30f;
            }
        }

        // 3) bf16 wmma: 128x128x128, warp tile 32x32
        wmma::fragment<wmma::accumulator, 16, 16, 16, float> fc[2][2];
#pragma unroll
        for (int r = 0; r < 2; r++)
#pragma unroll
            for (int c = 0; c < 2; c++) wmma::fill_fragment(fc[r][c], 0.f);

#pragma unroll
        for (int ks = 0; ks < 8; ks++) {
            const int k0 = ks * 16;
            wmma::fragment<wmma::matrix_a, 16, 16, 16, __nv_bfloat16, wmma::row_major> fa[2];
            wmma::fragment<wmma::matrix_b, 16, 16, 16, __nv_bfloat16, wmma::row_major> fb[2];
#pragma unroll
            for (int r = 0; r < 2; r++)
                wmma::load_matrix_sync(fa[r], A + (wr + r * 16) * LDA_H + k0, LDA_H);
#pragma unroll
            for (int c = 0; c < 2; c++)
                wmma::load_matrix_sync(fb[c], Bb + k0 * LDA_H + wc + c * 16, LDA_H);
#pragma unroll
            for (int r = 0; r < 2; r++)
#pragma unroll
                for (int c = 0; c < 2; c++)
                    wmma::mma_sync(fc[r][c], fa[r], fb[c], fc[r][c]);
        }

        // 4) all threads past epilogue reads of Cs, all warps past A reads of other buf users
        __syncthreads();

        // 5) store C frags; STS staged A[s+1]
#pragma unroll
        for (int r = 0; r < 2; r++)
#pragma unroll
            for (int c = 0; c < 2; c++)
                wmma::store_matrix_sync(Cs + (wr + r * 16) * LDC + wc + c * 16,
                                        fc[r][c], LDC, wmma::mem_row_major);
        if (s + 1 < I_PER_CTA) {
            __nv_bfloat16* dst = Ab[1 - (s & 1)];
#pragma unroll
            for (int t = 0; t < 4; t++) {
                int chunk = tid + t * 512;
                int row = chunk >> 4, c8 = (chunk & 15) * 8;
                float4 v0 = stage[2 * t], v1 = stage[2 * t + 1];
                __nv_bfloat162 p0 = __floats2bfloat162_rn(v0.x, v0.y);
                __nv_bfloat162 p1 = __floats2bfloat162_rn(v0.z, v0.w);
                __nv_bfloat162 p2 = __floats2bfloat162_rn(v1.x, v1.y);
                __nv_bfloat162 p3 = __floats2bfloat162_rn(v1.z, v1.w);
                uint4 o;
                o.x = *(uint32_t*)&p0; o.y = *(uint32_t*)&p1;
                o.z = *(uint32_t*)&p2; o.w = *(uint32_t*)&p3;
                *(uint4*)(dst + row * LDA_H + c8) = o;
            }
        }
        __syncthreads();
    }

    // final epilogue: tile 7
    {
        const int i = i_base + I_PER_CTA - 1;
        const int row = tid >> 2, q = tid & 3;
        const float* cr = Cs + row * LDC + q * 32;
        const float* br = g_base + (size_t)(j0 + row) * E + q * 32;
        const float* w2 = wa2s + q * 32;
        float part = 0.f;
#pragma unroll
        for (int c = 0; c < 32; c += 4) {
            float4 cv = *(const float4*)(cr + c);
            float4 bv = *(const float4*)(br + c);
            part = fmaf(lrelu(cv.x + bv.x), w2[c], part);
            part = fmaf(lrelu(cv.y + bv.y), w2[c + 1], part);
            part = fmaf(lrelu(cv.z + bv.z), w2[c + 2], part);
            part = fmaf(lrelu(cv.w + bv.w), w2[c + 3], part);
        }
        part += __shfl_xor_sync(0xffffffffu, part, 1);
        part += __shfl_xor_sync(0xffffffffu, part, 2);
        if (q == 0) {
            float lg = lrelu(g_s[i] + part + ab);
            size_t oidx = (size_t)i * N + j0 + row;
            g_logits[oidx] = (adj[oidx] == 1) ? lg : -1e30f;
        }
    }
}

// ---------------- softmax + attn@embs + concat ----------------
#define RPB 4
__global__ void __launch_bounds__(128)
k_out(const float* __restrict__ embs, float* __restrict__ out) {
    __shared__ float attn[RPB][N];
    __shared__ float red[E];
    const int i0 = blockIdx.x * RPB;
    const int t = threadIdx.x;

    float inv[RPB];
#pragma unroll
    for (int r = 0; r < RPB; r++) {
        const float* lg = g_logits + (size_t)(i0 + r) * N;
        float m = -1e30f;
#pragma unroll
        for (int q = 0; q < N / E; q++) m = fmaxf(m, lg[t + q * E]);
        red[t] = m;
        for (int off = 64; off > 0; off >>= 1) {
            __syncthreads();
            if (t < off) red[t] = fmaxf(red[t], red[t + off]);
        }
        __syncthreads();
        m = red[0];
        __syncthreads();
        float s = 0.f;
#pragma unroll
        for (int q = 0; q < N / E; q++) {
            float e = expf(lg[t + q * E] - m);
            attn[r][t + q * E] = e;
            s += e;
        }
        red[t] = s;
        for (int off = 64; off > 0; off >>= 1) {
            __syncthreads();
            if (t < off) red[t] += red[t + off];
        }
        __syncthreads();
        inv[r] = 1.f / red[0];
        __syncthreads();
    }

    float acc[RPB];
#pragma unroll
    for (int r = 0; r < RPB; r++) acc[r] = 0.f;
#pragma unroll 8
    for (int j = 0; j < N; j++) {
        float ev = embs[j * E + t];
#pragma unroll
        for (int r = 0; r < RPB; r++) acc[r] = fmaf(attn[r][j], ev, acc[r]);
    }
#pragma unroll
    for (int r = 0; r < RPB; r++) {
        int i = i0 + r;
        out[(size_t)i * (2 * E) + t] = embs[i * E + t];
        out[(size_t)i * (2 * E) + E + t] = acc[r] * inv[r];
    }
}

// ---------------- launch ----------------
extern "C" void kernel_launch(void* const* d_in, const int* in_sizes, int n_in,
                              void* d_out, int out_size) {
    const float* embs = (const float*)d_in[0];
    const int*   adj  = (const int*)d_in[1];
    const float* pde  = (const float*)d_in[2];
    const float* W    = (const float*)d_in[3];
    const float* pcW  = (const float*)d_in[4];
    const float* pcb  = (const float*)d_in[5];
    const float* aW   = (const float*)d_in[6];
    const float* ab   = (const float*)d_in[7];
    float* out = (float*)d_out;

    cudaFuncSetAttribute(k_big, cudaFuncAttributeMaxDynamicSharedMemorySize,
                         (int)SMEM_DYN);

    k_wf<<<N, E>>>(embs, W);
    k_wa2<<<1, E>>>(W, aW);
    k_base<<<N, E>>>(pcW, pcb, aW);
    k_bb<<<E, E>>>(pcW);
    k_big<<<dim3(8, N / I_PER_CTA), 512, SMEM_DYN>>>(pde, adj, ab);
    k_out<<<N / RPB, 128>>>(embs, out);
}